// round 12
// baseline (speedup 1.0000x reference)
#include <cuda_runtime.h>

// Problem constants (fixed-shape problem)
constexpr int Bc = 2, Hc = 12, Sc = 2048, Dc = 64, Gc = 128;
constexpr int KC = 16;
constexpr int QT = 128;
constexpr long CTX_ELEMS = (long)Bc * Hc * Sc * Dc;

// Scratch
__device__ int   d_gidx[Bc * Gc];
__device__ int   d_gcnt[Bc];
__device__ float d_pacc[(size_t)Bc * Hc * KC * Gc * Dc];
__device__ float d_pl[Bc * Hc * KC * Gc];

// Shared memory (floats):
//   qsT[64][128] @0, ksT[64][128] @8192   (probsT[128][128] overlays @0)
//   gvs[128][64] @16384, red[128][17] @24576, linv[128] @26752
constexpr int SM_FLOATS = 26880;
constexpr int SMEM_BYTES = SM_FLOATS * 4;   // 107520 B -> 2 CTAs/SM (smem-limited)

typedef unsigned long long ull;
__device__ __forceinline__ ull pack2(float x, float y) {
    ull r; asm("mov.b64 %0, {%1, %2};" : "=l"(r) : "f"(x), "f"(y)); return r;
}
__device__ __forceinline__ ull fma2(ull a, ull b, ull c) {
    ull d; asm("fma.rn.f32x2 %0, %1, %2, %3;" : "=l"(d) : "l"(a), "l"(b), "l"(c));
    return d;
}
__device__ __forceinline__ float2 unpack2(ull a) {
    float2 f; asm("mov.b64 {%0, %1}, %2;" : "=f"(f.x), "=f"(f.y) : "l"(a));
    return f;
}

// ---------------------------------------------------------------------------
// Zero-fill (parallel branch): probs cols [128,2048) for all rows.
// Grid: 12288 blocks x 4 rows (one row per warp), 128 threads.
// ---------------------------------------------------------------------------
__global__ void __launch_bounds__(128) fill_kernel(float* __restrict__ probs) {
    int w = threadIdx.x >> 5, lane = threadIdx.x & 31;
    size_t row = (size_t)blockIdx.x * 4 + w;
    float4 z = make_float4(0.f, 0.f, 0.f, 0.f);
    float4* p = (float4*)(probs + row * Sc + 128);
#pragma unroll
    for (int cc = lane; cc < 480; cc += 32) __stcs(p + cc, z);
}

__global__ void dummy_kernel() {}

// ---------------------------------------------------------------------------
__global__ void build_index_kernel(const int* __restrict__ mask) {
    int b = blockIdx.x;
    __shared__ int wtot[8];
    int tid = threadIdx.x, lane = tid & 31, w = tid >> 5;
    const int SEG = Sc / 256;
    int base = tid * SEG;
    int mv[SEG];
    int c = 0;
#pragma unroll
    for (int i = 0; i < SEG; i++) { mv[i] = mask[b * Sc + base + i] > 0; c += mv[i]; }
    int sc = c;
#pragma unroll
    for (int d = 1; d < 32; d <<= 1) {
        int t = __shfl_up_sync(0xffffffffu, sc, d);
        if (lane >= d) sc += t;
    }
    if (lane == 31) wtot[w] = sc;
    __syncthreads();
    int woff = 0;
#pragma unroll
    for (int t = 0; t < 8; t++) woff += (t < w) ? wtot[t] : 0;
    if (tid == 0) {
        int s = 0;
#pragma unroll
        for (int t = 0; t < 8; t++) s += wtot[t];
        d_gcnt[b] = (s < Gc) ? s : Gc;
    }
    int o = woff + sc - c;
#pragma unroll
    for (int i = 0; i < SEG; i++) {
        if (mv[i]) {
            if (o < Gc) d_gidx[b * Gc + o] = base + i;
            o++;
        }
    }
}

// ---------------------------------------------------------------------------
// Fused compute kernel (R7 config, 112-reg cap; occupancy 2 forced by smem).
// Grid (32, H, B), 256 threads:
//   x in [0,16)  -> roleB: global-branch attn + probs cols [0,128) + ctx
//   x in [16,32) -> roleC: split-KV chunk of full attn for global queries
// ---------------------------------------------------------------------------
__global__ void __maxnreg__(112) fused_attn_kernel(
    const float* __restrict__ q, const float* __restrict__ k,
    const float* __restrict__ v, float* __restrict__ ctx,
    float* __restrict__ probs) {
    extern __shared__ float sm[];
    float* qsT    = sm;            // [64][128]
    float* ksT    = sm + 8192;     // [64][128]
    float* probsT = sm;            // [128 key][128 query], overlays after GEMM1
    float* gvs    = sm + 16384;    // [128][64]
    float* red    = sm + 24576;    // [128][17]
    float* linv   = sm + 26752;    // [128]

    int tid = threadIdx.x;
    int h = blockIdx.y, b = blockIdx.z;
    int bh = b * Hc + h;

    bool roleB = blockIdx.x < 16;
    int q0 = roleB ? blockIdx.x * QT : 0;
    int kc = roleB ? 0 : blockIdx.x - 16;
    int k0 = kc * 128;
    int c = d_gcnt[b];

    const float* qb = q + (size_t)bh * Sc * Dc;
    const float* kb = k + (size_t)bh * Sc * Dc;
    const float* vb = v + (size_t)bh * Sc * Dc;

    // ---- Load phase
    {
        int r = tid & 127, half = tid >> 7;
        int d0base = half * 32;

        bool qvalid = roleB || (r < c);
        int qrowi = roleB ? (q0 + r) : (qvalid ? d_gidx[b * Gc + r] : 0);
        const float* qrow = qb + (size_t)qrowi * Dc;
#pragma unroll
        for (int d0 = 0; d0 < 32; d0 += 4) {
            int dd = d0base + d0;
            float4 t = qvalid ? *(const float4*)(qrow + dd)
                              : make_float4(0.f, 0.f, 0.f, 0.f);
            qsT[(dd + 0) * 128 + r] = t.x;
            qsT[(dd + 1) * 128 + r] = t.y;
            qsT[(dd + 2) * 128 + r] = t.z;
            qsT[(dd + 3) * 128 + r] = t.w;
        }

        bool kvalid = roleB ? (r < c) : true;
        int krowi = roleB ? (kvalid ? d_gidx[b * Gc + r] : 0) : (k0 + r);
        const float* krow = kb + (size_t)krowi * Dc;
        const float* vrow = vb + (size_t)krowi * Dc;
#pragma unroll
        for (int d0 = 0; d0 < 32; d0 += 4) {
            int dd = d0base + d0;
            float4 t = kvalid ? *(const float4*)(krow + dd)
                              : make_float4(0.f, 0.f, 0.f, 0.f);
            ksT[(dd + 0) * 128 + r] = t.x;
            ksT[(dd + 1) * 128 + r] = t.y;
            ksT[(dd + 2) * 128 + r] = t.z;
            ksT[(dd + 3) * 128 + r] = t.w;
            *(float4*)(gvs + r * 64 + dd) = kvalid ? *(const float4*)(vrow + dd)
                                                   : make_float4(0.f, 0.f, 0.f, 0.f);
        }
    }
    __syncthreads();

    // ---- GEMM1: S^T[128 key][128 query], 8x8/thread, conflict-free.
    int lane = tid & 31, w = tid >> 5;
    int qx = (lane & 7) | ((w & 1) << 3);
    int kg = (lane >> 3) | ((w >> 1) << 2);
    int kg8 = kg * 8, qx4 = qx * 4;

    int colw[8];
#pragma unroll
    for (int jj = 0; jj < 8; jj++) colw[jj] = (jj < 4) ? (qx4 + jj) : (60 + qx4 + jj);

    ull acc2[8][4];
#pragma unroll
    for (int i = 0; i < 8; i++)
#pragma unroll
        for (int jp = 0; jp < 4; jp++) acc2[i][jp] = 0ull;

#pragma unroll 8
    for (int d = 0; d < 64; d++) {
        const float4* kk = (const float4*)(ksT + d * 128 + kg8);
        float4 kv0 = kk[0], kv1 = kk[1];
        ull ap[8];
        ap[0] = pack2(kv0.x, kv0.x); ap[1] = pack2(kv0.y, kv0.y);
        ap[2] = pack2(kv0.z, kv0.z); ap[3] = pack2(kv0.w, kv0.w);
        ap[4] = pack2(kv1.x, kv1.x); ap[5] = pack2(kv1.y, kv1.y);
        ap[6] = pack2(kv1.z, kv1.z); ap[7] = pack2(kv1.w, kv1.w);
        ulonglong2 qA = *(const ulonglong2*)(qsT + d * 128 + qx4);
        ulonglong2 qB = *(const ulonglong2*)(qsT + d * 128 + 64 + qx4);
#pragma unroll
        for (int i = 0; i < 8; i++) {
            acc2[i][0] = fma2(ap[i], qA.x, acc2[i][0]);
            acc2[i][1] = fma2(ap[i], qA.y, acc2[i][1]);
            acc2[i][2] = fma2(ap[i], qB.x, acc2[i][2]);
            acc2[i][3] = fma2(ap[i], qB.y, acc2[i][3]);
        }
    }
    __syncthreads();   // all GEMM1 reads of qsT/ksT done before probsT overwrite

    // ---- softmax (no max-sub): exp in place, write probsT, column sums
    {
        float cs[8];
#pragma unroll
        for (int jj = 0; jj < 8; jj++) cs[jj] = 0.f;
#pragma unroll
        for (int i = 0; i < 8; i++) {
            bool kval = (!roleB) || (kg8 + i < c);
#pragma unroll
            for (int jp = 0; jp < 4; jp++) {
                float2 f = unpack2(acc2[i][jp]);
                float e0 = kval ? __expf(f.x * 0.125f) : 0.f;
                float e1 = kval ? __expf(f.y * 0.125f) : 0.f;
                acc2[i][jp] = pack2(e0, e1);
                cs[2 * jp]     += e0;
                cs[2 * jp + 1] += e1;
            }
            *(ulonglong2*)(probsT + (kg8 + i) * 128 + qx4) =
                make_ulonglong2(acc2[i][0], acc2[i][1]);
            *(ulonglong2*)(probsT + (kg8 + i) * 128 + 64 + qx4) =
                make_ulonglong2(acc2[i][2], acc2[i][3]);
        }
#pragma unroll
        for (int jj = 0; jj < 8; jj++) red[colw[jj] * 17 + kg] = cs[jj];
    }
    __syncthreads();
    if (tid < 128) {
        float rs = 0.f;
#pragma unroll
        for (int g = 0; g < 16; g++) rs += red[tid * 17 + g];
        linv[tid] = 1.0f / rs;
        if (!roleB) d_pl[((size_t)bh * KC + kc) * Gc + tid] = rs;
    }
    __syncthreads();

    // ---- probs gmem write straight from registers (roleB only)
    if (roleB) {
        float lv[8];
#pragma unroll
        for (int jj = 0; jj < 8; jj++) lv[jj] = linv[colw[jj]];
#pragma unroll
        for (int jp = 0; jp < 4; jp++) {
            float2 f[8];
#pragma unroll
            for (int i = 0; i < 8; i++) f[i] = unpack2(acc2[i][jp]);
            float l0 = lv[2 * jp], l1 = lv[2 * jp + 1];
            float* r0 = probs + ((size_t)bh * Sc + q0 + colw[2 * jp]) * Sc + kg8;
            float* r1 = probs + ((size_t)bh * Sc + q0 + colw[2 * jp + 1]) * Sc + kg8;
            __stcs((float4*)r0, make_float4(f[0].x * l0, f[1].x * l0, f[2].x * l0, f[3].x * l0));
            __stcs((float4*)(r0 + 4), make_float4(f[4].x * l0, f[5].x * l0, f[6].x * l0, f[7].x * l0));
            __stcs((float4*)r1, make_float4(f[0].y * l1, f[1].y * l1, f[2].y * l1, f[3].y * l1));
            __stcs((float4*)(r1 + 4), make_float4(f[4].y * l1, f[5].y * l1, f[6].y * l1, f[7].y * l1));
        }
    }

    // ---- GEMM2: C[128 q][64 d] = probsT^T @ V. 4 rows x 8 cols per thread.
    {
        int dg = lane & 7;
        int rg = (lane >> 3) | (w << 2);
        int dg4 = dg * 4, rg4 = rg * 4;

        ull ag[4][4];
#pragma unroll
        for (int r = 0; r < 4; r++)
#pragma unroll
            for (int p = 0; p < 4; p++) ag[r][p] = 0ull;

#pragma unroll 8
        for (int j = 0; j < 128; j++) {
            float4 av = *(const float4*)(probsT + j * 128 + rg4);
            ull p0 = pack2(av.x, av.x), p1 = pack2(av.y, av.y);
            ull p2 = pack2(av.z, av.z), p3 = pack2(av.w, av.w);
            ulonglong2 vA = *(const ulonglong2*)(gvs + j * 64 + dg4);
            ulonglong2 vB = *(const ulonglong2*)(gvs + j * 64 + 32 + dg4);
            ag[0][0] = fma2(p0, vA.x, ag[0][0]); ag[0][1] = fma2(p0, vA.y, ag[0][1]);
            ag[0][2] = fma2(p0, vB.x, ag[0][2]); ag[0][3] = fma2(p0, vB.y, ag[0][3]);
            ag[1][0] = fma2(p1, vA.x, ag[1][0]); ag[1][1] = fma2(p1, vA.y, ag[1][1]);
            ag[1][2] = fma2(p1, vB.x, ag[1][2]); ag[1][3] = fma2(p1, vB.y, ag[1][3]);
            ag[2][0] = fma2(p2, vA.x, ag[2][0]); ag[2][1] = fma2(p2, vA.y, ag[2][1]);
            ag[2][2] = fma2(p2, vB.x, ag[2][2]); ag[2][3] = fma2(p2, vB.y, ag[2][3]);
            ag[3][0] = fma2(p3, vA.x, ag[3][0]); ag[3][1] = fma2(p3, vA.y, ag[3][1]);
            ag[3][2] = fma2(p3, vB.x, ag[3][2]); ag[3][3] = fma2(p3, vB.y, ag[3][3]);
        }

        if (roleB) {
#pragma unroll
            for (int r = 0; r < 4; r++) {
                float lv = linv[rg4 + r];
                float* orow = ctx + ((size_t)bh * Sc + q0 + rg4 + r) * Dc;
                float2 f0 = unpack2(ag[r][0]), f1 = unpack2(ag[r][1]);
                float2 f2 = unpack2(ag[r][2]), f3 = unpack2(ag[r][3]);
                *(float4*)(orow + dg4) =
                    make_float4(f0.x * lv, f0.y * lv, f1.x * lv, f1.y * lv);
                *(float4*)(orow + 32 + dg4) =
                    make_float4(f2.x * lv, f2.y * lv, f3.x * lv, f3.y * lv);
            }
        } else {
#pragma unroll
            for (int r = 0; r < 4; r++) {
                float* orow = d_pacc + (((size_t)bh * KC + kc) * Gc + rg4 + r) * Dc;
                float2 f0 = unpack2(ag[r][0]), f1 = unpack2(ag[r][1]);
                float2 f2 = unpack2(ag[r][2]), f3 = unpack2(ag[r][3]);
                *(float4*)(orow + dg4) = make_float4(f0.x, f0.y, f1.x, f1.y);
                *(float4*)(orow + 32 + dg4) = make_float4(f2.x, f2.y, f3.x, f3.y);
            }
        }
    }
}

// ---------------------------------------------------------------------------
// Combine: plain sum of KC split-KV partials.
// ---------------------------------------------------------------------------
__global__ void combine_kernel(float* __restrict__ ctx) {
    int bh = blockIdx.x;
    int b = bh / Hc;
    int c = d_gcnt[b];
    int tid = threadIdx.x;
    int rl = tid >> 4, seg = tid & 15;
    int r = blockIdx.y * 16 + rl;
    if (r >= c) return;

    float L = 0.f;
    float4 s = make_float4(0.f, 0.f, 0.f, 0.f);
#pragma unroll
    for (int kc = 0; kc < KC; kc++) {
        L += d_pl[((size_t)bh * KC + kc) * Gc + r];
        float4 g = *(const float4*)(d_pacc +
            (((size_t)bh * KC + kc) * Gc + r) * (size_t)Dc + seg * 4);
        s.x += g.x; s.y += g.y; s.z += g.z; s.w += g.w;
    }
    float inv = 1.0f / L;
    int gi = d_gidx[b * Gc + r];
    *(float4*)(ctx + ((size_t)bh * Sc + gi) * Dc + seg * 4) =
        make_float4(s.x * inv, s.y * inv, s.z * inv, s.w * inv);
}

// ---------------------------------------------------------------------------
// Launch: BOTH branches live on non-blocking streams; the legacy stream 0
// only carries the fork event and the final joins, so the captured graph has
// genuine parallel edges (legacy-stream nodes serialize against everything).
// ---------------------------------------------------------------------------
extern "C" void kernel_launch(void* const* d_in, const int* in_sizes, int n_in,
                              void* d_out, int out_size) {
    const float* q = (const float*)d_in[0];
    const float* k = (const float*)d_in[1];
    const float* v = (const float*)d_in[2];
    const int* mask = (const int*)d_in[3];

    float* ctx = (float*)d_out;
    float* probs = ctx + CTX_ELEMS;

    static cudaStream_t s1, s2;
    static cudaEvent_t e1, eA, eB;
    static bool inited = false;
    if (!inited) {
        cudaStreamCreateWithFlags(&s1, cudaStreamNonBlocking);
        cudaStreamCreateWithFlags(&s2, cudaStreamNonBlocking);
        cudaEventCreateWithFlags(&e1, cudaEventDisableTiming);
        cudaEventCreateWithFlags(&eA, cudaEventDisableTiming);
        cudaEventCreateWithFlags(&eB, cudaEventDisableTiming);
        inited = true;
    }

    cudaFuncSetAttribute(fused_attn_kernel,
                         cudaFuncAttributeMaxDynamicSharedMemorySize, SMEM_BYTES);

    // Fork from the capture origin (legacy stream 0).
    cudaEventRecord(e1, 0);
    cudaStreamWaitEvent(s1, e1, 0);
    cudaStreamWaitEvent(s2, e1, 0);

    // Branch 2: zero-fill (parallel with the whole compute chain).
    fill_kernel<<<12288, 128, 0, s2>>>(probs);         // launch idx 0
    cudaEventRecord(eB, s2);

    // Branch 1: compute chain.
    dummy_kernel<<<1, 1, 0, s1>>>();                   // launch idx 1
    build_index_kernel<<<Bc, 256, 0, s1>>>(mask);      // launch idx 2
    fused_attn_kernel<<<dim3(32, Hc, Bc), 256, SMEM_BYTES, s1>>>(q, k, v, ctx, probs);  // idx 3 (ncu)
    combine_kernel<<<dim3(Bc * Hc, 8), 256, 0, s1>>>(ctx);  // launch idx 4
    cudaEventRecord(eA, s1);

    // Join both branches back into stream 0.
    cudaStreamWaitEvent(0, eA, 0);
    cudaStreamWaitEvent(0, eB, 0);
}

// round 13
// speedup vs baseline: 1.1927x; 1.1927x over previous
#include <cuda_runtime.h>

// Problem constants (fixed-shape problem)
constexpr int Bc = 2, Hc = 12, Sc = 2048, Dc = 64, Gc = 128;
constexpr int KC = 16;
constexpr int QT = 128;
constexpr long CTX_ELEMS = (long)Bc * Hc * Sc * Dc;

// Scratch
__device__ int   d_gidx[Bc * Gc];
__device__ int   d_gcnt[Bc];
__device__ float d_pacc[(size_t)Bc * Hc * KC * Gc * Dc];
__device__ float d_pl[Bc * Hc * KC * Gc];

// Shared memory (floats):
//   qsT[64][128] @0, ksT[64][128] @8192   (probsT[128][128] overlays @0)
//   gvs[128][64] @16384, red[128][17] @24576, linv[128] @26752
constexpr int SM_FLOATS = 26880;
constexpr int SMEM_BYTES = SM_FLOATS * 4;   // 107520 B -> 2 CTAs/SM (smem-limited)

typedef unsigned long long ull;
__device__ __forceinline__ ull pack2(float x, float y) {
    ull r; asm("mov.b64 %0, {%1, %2};" : "=l"(r) : "f"(x), "f"(y)); return r;
}
__device__ __forceinline__ ull fma2(ull a, ull b, ull c) {
    ull d; asm("fma.rn.f32x2 %0, %1, %2, %3;" : "=l"(d) : "l"(a), "l"(b), "l"(c));
    return d;
}
__device__ __forceinline__ float2 unpack2(ull a) {
    float2 f; asm("mov.b64 {%0, %1}, %2;" : "=f"(f.x), "=f"(f.y) : "l"(a));
    return f;
}

__global__ void dummy_kernel() {}

// ---------------------------------------------------------------------------
__global__ void build_index_kernel(const int* __restrict__ mask) {
    int b = blockIdx.x;
    __shared__ int wtot[8];
    int tid = threadIdx.x, lane = tid & 31, w = tid >> 5;
    const int SEG = Sc / 256;
    int base = tid * SEG;
    int mv[SEG];
    int c = 0;
#pragma unroll
    for (int i = 0; i < SEG; i++) { mv[i] = mask[b * Sc + base + i] > 0; c += mv[i]; }
    int sc = c;
#pragma unroll
    for (int d = 1; d < 32; d <<= 1) {
        int t = __shfl_up_sync(0xffffffffu, sc, d);
        if (lane >= d) sc += t;
    }
    if (lane == 31) wtot[w] = sc;
    __syncthreads();
    int woff = 0;
#pragma unroll
    for (int t = 0; t < 8; t++) woff += (t < w) ? wtot[t] : 0;
    if (tid == 0) {
        int s = 0;
#pragma unroll
        for (int t = 0; t < 8; t++) s += wtot[t];
        d_gcnt[b] = (s < Gc) ? s : Gc;
    }
    int o = woff + sc - c;
#pragma unroll
    for (int i = 0; i < SEG; i++) {
        if (mv[i]) {
            if (o < Gc) d_gidx[b * Gc + o] = base + i;
            o++;
        }
    }
}

// ---------------------------------------------------------------------------
// Fused compute kernel with EMBEDDED zero-fill prologue.
// Grid (32, H, B), 256 threads:
//   every CTA first fire-and-forget streams its 32-row share of the probs
//   zero region (cols [128,2048)), then computes its role:
//   x in [0,16)  -> roleB: global-branch attn + probs cols [0,128) + ctx
//   x in [16,32) -> roleC: split-KV chunk of full attn for global queries
// The ~50us DRAM store drain overlaps the ~100us smem/FMA-bound compute
// inside one kernel (kernel-level concurrency proved impossible, R8-R12).
// ---------------------------------------------------------------------------
__global__ void __launch_bounds__(256, 2) fused_attn_kernel(
    const float* __restrict__ q, const float* __restrict__ k,
    const float* __restrict__ v, float* __restrict__ ctx,
    float* __restrict__ probs) {
    extern __shared__ float sm[];
    float* qsT    = sm;            // [64][128]
    float* ksT    = sm + 8192;     // [64][128]
    float* probsT = sm;            // [128 key][128 query], overlays after GEMM1
    float* gvs    = sm + 16384;    // [128][64]
    float* red    = sm + 24576;    // [128][17]
    float* linv   = sm + 26752;    // [128]

    int tid = threadIdx.x;
    int h = blockIdx.y, b = blockIdx.z;
    int bh = b * Hc + h;

    // ---- Zero-fill prologue: this CTA's 32 rows of probs cols [128,2048).
    // Independent streaming stores issued before any dependency; the DRAM
    // drain overlaps the whole compute phase below.
    {
        int cid = blockIdx.x + 32 * (blockIdx.y + Hc * blockIdx.z);   // 0..767
        int w8 = tid >> 5, lane = tid & 31;
        float4 z = make_float4(0.f, 0.f, 0.f, 0.f);
        size_t row0 = (size_t)cid * 32 + (size_t)w8 * 4;
#pragma unroll
        for (int r = 0; r < 4; r++) {
            float4* p = (float4*)(probs + (row0 + r) * Sc + 128);
#pragma unroll 3
            for (int cc = lane; cc < 480; cc += 32) __stcs(p + cc, z);
        }
    }

    bool roleB = blockIdx.x < 16;
    int q0 = roleB ? blockIdx.x * QT : 0;
    int kc = roleB ? 0 : blockIdx.x - 16;
    int k0 = kc * 128;
    int c = d_gcnt[b];

    const float* qb = q + (size_t)bh * Sc * Dc;
    const float* kb = k + (size_t)bh * Sc * Dc;
    const float* vb = v + (size_t)bh * Sc * Dc;

    // ---- Load phase
    {
        int r = tid & 127, half = tid >> 7;
        int d0base = half * 32;

        bool qvalid = roleB || (r < c);
        int qrowi = roleB ? (q0 + r) : (qvalid ? d_gidx[b * Gc + r] : 0);
        const float* qrow = qb + (size_t)qrowi * Dc;
#pragma unroll
        for (int d0 = 0; d0 < 32; d0 += 4) {
            int dd = d0base + d0;
            float4 t = qvalid ? *(const float4*)(qrow + dd)
                              : make_float4(0.f, 0.f, 0.f, 0.f);
            qsT[(dd + 0) * 128 + r] = t.x;
            qsT[(dd + 1) * 128 + r] = t.y;
            qsT[(dd + 2) * 128 + r] = t.z;
            qsT[(dd + 3) * 128 + r] = t.w;
        }

        bool kvalid = roleB ? (r < c) : true;
        int krowi = roleB ? (kvalid ? d_gidx[b * Gc + r] : 0) : (k0 + r);
        const float* krow = kb + (size_t)krowi * Dc;
        const float* vrow = vb + (size_t)krowi * Dc;
#pragma unroll
        for (int d0 = 0; d0 < 32; d0 += 4) {
            int dd = d0base + d0;
            float4 t = kvalid ? *(const float4*)(krow + dd)
                              : make_float4(0.f, 0.f, 0.f, 0.f);
            ksT[(dd + 0) * 128 + r] = t.x;
            ksT[(dd + 1) * 128 + r] = t.y;
            ksT[(dd + 2) * 128 + r] = t.z;
            ksT[(dd + 3) * 128 + r] = t.w;
            *(float4*)(gvs + r * 64 + dd) = kvalid ? *(const float4*)(vrow + dd)
                                                   : make_float4(0.f, 0.f, 0.f, 0.f);
        }
    }
    __syncthreads();

    // ---- GEMM1: S^T[128 key][128 query], 8x8/thread, conflict-free.
    int lane = tid & 31, w = tid >> 5;
    int qx = (lane & 7) | ((w & 1) << 3);
    int kg = (lane >> 3) | ((w >> 1) << 2);
    int kg8 = kg * 8, qx4 = qx * 4;

    int colw[8];
#pragma unroll
    for (int jj = 0; jj < 8; jj++) colw[jj] = (jj < 4) ? (qx4 + jj) : (60 + qx4 + jj);

    ull acc2[8][4];
#pragma unroll
    for (int i = 0; i < 8; i++)
#pragma unroll
        for (int jp = 0; jp < 4; jp++) acc2[i][jp] = 0ull;

#pragma unroll 8
    for (int d = 0; d < 64; d++) {
        const float4* kk = (const float4*)(ksT + d * 128 + kg8);
        float4 kv0 = kk[0], kv1 = kk[1];
        ull ap[8];
        ap[0] = pack2(kv0.x, kv0.x); ap[1] = pack2(kv0.y, kv0.y);
        ap[2] = pack2(kv0.z, kv0.z); ap[3] = pack2(kv0.w, kv0.w);
        ap[4] = pack2(kv1.x, kv1.x); ap[5] = pack2(kv1.y, kv1.y);
        ap[6] = pack2(kv1.z, kv1.z); ap[7] = pack2(kv1.w, kv1.w);
        ulonglong2 qA = *(const ulonglong2*)(qsT + d * 128 + qx4);
        ulonglong2 qB = *(const ulonglong2*)(qsT + d * 128 + 64 + qx4);
#pragma unroll
        for (int i = 0; i < 8; i++) {
            acc2[i][0] = fma2(ap[i], qA.x, acc2[i][0]);
            acc2[i][1] = fma2(ap[i], qA.y, acc2[i][1]);
            acc2[i][2] = fma2(ap[i], qB.x, acc2[i][2]);
            acc2[i][3] = fma2(ap[i], qB.y, acc2[i][3]);
        }
    }
    __syncthreads();   // all GEMM1 reads of qsT/ksT done before probsT overwrite

    // ---- softmax (no max-sub): exp in place, write probsT, column sums
    {
        float cs[8];
#pragma unroll
        for (int jj = 0; jj < 8; jj++) cs[jj] = 0.f;
#pragma unroll
        for (int i = 0; i < 8; i++) {
            bool kval = (!roleB) || (kg8 + i < c);
#pragma unroll
            for (int jp = 0; jp < 4; jp++) {
                float2 f = unpack2(acc2[i][jp]);
                float e0 = kval ? __expf(f.x * 0.125f) : 0.f;
                float e1 = kval ? __expf(f.y * 0.125f) : 0.f;
                acc2[i][jp] = pack2(e0, e1);
                cs[2 * jp]     += e0;
                cs[2 * jp + 1] += e1;
            }
            *(ulonglong2*)(probsT + (kg8 + i) * 128 + qx4) =
                make_ulonglong2(acc2[i][0], acc2[i][1]);
            *(ulonglong2*)(probsT + (kg8 + i) * 128 + 64 + qx4) =
                make_ulonglong2(acc2[i][2], acc2[i][3]);
        }
#pragma unroll
        for (int jj = 0; jj < 8; jj++) red[colw[jj] * 17 + kg] = cs[jj];
    }
    __syncthreads();
    if (tid < 128) {
        float rs = 0.f;
#pragma unroll
        for (int g = 0; g < 16; g++) rs += red[tid * 17 + g];
        linv[tid] = 1.0f / rs;
        if (!roleB) d_pl[((size_t)bh * KC + kc) * Gc + tid] = rs;
    }
    __syncthreads();

    // ---- probs gmem write straight from registers (roleB only)
    if (roleB) {
        float lv[8];
#pragma unroll
        for (int jj = 0; jj < 8; jj++) lv[jj] = linv[colw[jj]];
#pragma unroll
        for (int jp = 0; jp < 4; jp++) {
            float2 f[8];
#pragma unroll
            for (int i = 0; i < 8; i++) f[i] = unpack2(acc2[i][jp]);
            float l0 = lv[2 * jp], l1 = lv[2 * jp + 1];
            float* r0 = probs + ((size_t)bh * Sc + q0 + colw[2 * jp]) * Sc + kg8;
            float* r1 = probs + ((size_t)bh * Sc + q0 + colw[2 * jp + 1]) * Sc + kg8;
            __stcs((float4*)r0, make_float4(f[0].x * l0, f[1].x * l0, f[2].x * l0, f[3].x * l0));
            __stcs((float4*)(r0 + 4), make_float4(f[4].x * l0, f[5].x * l0, f[6].x * l0, f[7].x * l0));
            __stcs((float4*)r1, make_float4(f[0].y * l1, f[1].y * l1, f[2].y * l1, f[3].y * l1));
            __stcs((float4*)(r1 + 4), make_float4(f[4].y * l1, f[5].y * l1, f[6].y * l1, f[7].y * l1));
        }
    }

    // ---- GEMM2: C[128 q][64 d] = probsT^T @ V. 4 rows x 8 cols per thread.
    {
        int dg = lane & 7;
        int rg = (lane >> 3) | (w << 2);
        int dg4 = dg * 4, rg4 = rg * 4;

        ull ag[4][4];
#pragma unroll
        for (int r = 0; r < 4; r++)
#pragma unroll
            for (int p = 0; p < 4; p++) ag[r][p] = 0ull;

#pragma unroll 8
        for (int j = 0; j < 128; j++) {
            float4 av = *(const float4*)(probsT + j * 128 + rg4);
            ull p0 = pack2(av.x, av.x), p1 = pack2(av.y, av.y);
            ull p2 = pack2(av.z, av.z), p3 = pack2(av.w, av.w);
            ulonglong2 vA = *(const ulonglong2*)(gvs + j * 64 + dg4);
            ulonglong2 vB = *(const ulonglong2*)(gvs + j * 64 + 32 + dg4);
            ag[0][0] = fma2(p0, vA.x, ag[0][0]); ag[0][1] = fma2(p0, vA.y, ag[0][1]);
            ag[0][2] = fma2(p0, vB.x, ag[0][2]); ag[0][3] = fma2(p0, vB.y, ag[0][3]);
            ag[1][0] = fma2(p1, vA.x, ag[1][0]); ag[1][1] = fma2(p1, vA.y, ag[1][1]);
            ag[1][2] = fma2(p1, vB.x, ag[1][2]); ag[1][3] = fma2(p1, vB.y, ag[1][3]);
            ag[2][0] = fma2(p2, vA.x, ag[2][0]); ag[2][1] = fma2(p2, vA.y, ag[2][1]);
            ag[2][2] = fma2(p2, vB.x, ag[2][2]); ag[2][3] = fma2(p2, vB.y, ag[2][3]);
            ag[3][0] = fma2(p3, vA.x, ag[3][0]); ag[3][1] = fma2(p3, vA.y, ag[3][1]);
            ag[3][2] = fma2(p3, vB.x, ag[3][2]); ag[3][3] = fma2(p3, vB.y, ag[3][3]);
        }

        if (roleB) {
#pragma unroll
            for (int r = 0; r < 4; r++) {
                float lv = linv[rg4 + r];
                float* orow = ctx + ((size_t)bh * Sc + q0 + rg4 + r) * Dc;
                float2 f0 = unpack2(ag[r][0]), f1 = unpack2(ag[r][1]);
                float2 f2 = unpack2(ag[r][2]), f3 = unpack2(ag[r][3]);
                *(float4*)(orow + dg4) =
                    make_float4(f0.x * lv, f0.y * lv, f1.x * lv, f1.y * lv);
                *(float4*)(orow + 32 + dg4) =
                    make_float4(f2.x * lv, f2.y * lv, f3.x * lv, f3.y * lv);
            }
        } else {
#pragma unroll
            for (int r = 0; r < 4; r++) {
                float* orow = d_pacc + (((size_t)bh * KC + kc) * Gc + rg4 + r) * Dc;
                float2 f0 = unpack2(ag[r][0]), f1 = unpack2(ag[r][1]);
                float2 f2 = unpack2(ag[r][2]), f3 = unpack2(ag[r][3]);
                *(float4*)(orow + dg4) = make_float4(f0.x, f0.y, f1.x, f1.y);
                *(float4*)(orow + 32 + dg4) = make_float4(f2.x, f2.y, f3.x, f3.y);
            }
        }
    }
}

// ---------------------------------------------------------------------------
// Combine: plain sum of KC split-KV partials.
// ---------------------------------------------------------------------------
__global__ void combine_kernel(float* __restrict__ ctx) {
    int bh = blockIdx.x;
    int b = bh / Hc;
    int c = d_gcnt[b];
    int tid = threadIdx.x;
    int rl = tid >> 4, seg = tid & 15;
    int r = blockIdx.y * 16 + rl;
    if (r >= c) return;

    float L = 0.f;
    float4 s = make_float4(0.f, 0.f, 0.f, 0.f);
#pragma unroll
    for (int kc = 0; kc < KC; kc++) {
        L += d_pl[((size_t)bh * KC + kc) * Gc + r];
        float4 g = *(const float4*)(d_pacc +
            (((size_t)bh * KC + kc) * Gc + r) * (size_t)Dc + seg * 4);
        s.x += g.x; s.y += g.y; s.z += g.z; s.w += g.w;
    }
    float inv = 1.0f / L;
    int gi = d_gidx[b * Gc + r];
    *(float4*)(ctx + ((size_t)bh * Sc + gi) * Dc + seg * 4) =
        make_float4(s.x * inv, s.y * inv, s.z * inv, s.w * inv);
}

// ---------------------------------------------------------------------------
extern "C" void kernel_launch(void* const* d_in, const int* in_sizes, int n_in,
                              void* d_out, int out_size) {
    const float* q = (const float*)d_in[0];
    const float* k = (const float*)d_in[1];
    const float* v = (const float*)d_in[2];
    const int* mask = (const int*)d_in[3];

    float* ctx = (float*)d_out;
    float* probs = ctx + CTX_ELEMS;

    cudaFuncSetAttribute(fused_attn_kernel,
                         cudaFuncAttributeMaxDynamicSharedMemorySize, SMEM_BYTES);

    dummy_kernel<<<1, 1>>>();                          // launch idx 0
    dummy_kernel<<<1, 1>>>();                          // launch idx 1
    build_index_kernel<<<Bc, 256>>>(mask);             // launch idx 2
    fused_attn_kernel<<<dim3(32, Hc, Bc), 256, SMEM_BYTES>>>(q, k, v, ctx, probs);  // idx 3 (ncu)
    combine_kernel<<<dim3(Bc * Hc, 8), 256>>>(ctx);    // launch idx 4
}

// round 14
// speedup vs baseline: 1.2620x; 1.0581x over previous
#include <cuda_runtime.h>

// Problem constants (fixed-shape problem)
constexpr int Bc = 2, Hc = 12, Sc = 2048, Dc = 64, Gc = 128;
constexpr int KC = 16;
constexpr int QT = 128;
constexpr long CTX_ELEMS = (long)Bc * Hc * Sc * Dc;

// Scratch
__device__ int   d_gidx[Bc * Gc];
__device__ int   d_gcnt[Bc];
__device__ float d_pacc[(size_t)Bc * Hc * KC * Gc * Dc];
__device__ float d_pl[Bc * Hc * KC * Gc];

// Shared memory (floats):
//   qsT[64][128] @0, ksT[64][128] @8192   (probsT[128][128] overlays @0)
//   gvs[128][64] @16384, red[128][17] @24576, linv[128] @26752
constexpr int SM_FLOATS = 26880;
constexpr int SMEM_BYTES = SM_FLOATS * 4;   // 107520 B -> 2 CTAs/SM (smem-limited)

typedef unsigned long long ull;
__device__ __forceinline__ ull pack2(float x, float y) {
    ull r; asm("mov.b64 %0, {%1, %2};" : "=l"(r) : "f"(x), "f"(y)); return r;
}
__device__ __forceinline__ ull fma2(ull a, ull b, ull c) {
    ull d; asm("fma.rn.f32x2 %0, %1, %2, %3;" : "=l"(d) : "l"(a), "l"(b), "l"(c));
    return d;
}
__device__ __forceinline__ float2 unpack2(ull a) {
    float2 f; asm("mov.b64 {%0, %1}, %2;" : "=f"(f.x), "=f"(f.y) : "l"(a));
    return f;
}

__global__ void dummy_kernel() {}

// ---------------------------------------------------------------------------
__global__ void build_index_kernel(const int* __restrict__ mask) {
    int b = blockIdx.x;
    __shared__ int wtot[8];
    int tid = threadIdx.x, lane = tid & 31, w = tid >> 5;
    const int SEG = Sc / 256;
    int base = tid * SEG;
    int mv[SEG];
    int c = 0;
#pragma unroll
    for (int i = 0; i < SEG; i++) { mv[i] = mask[b * Sc + base + i] > 0; c += mv[i]; }
    int sc = c;
#pragma unroll
    for (int d = 1; d < 32; d <<= 1) {
        int t = __shfl_up_sync(0xffffffffu, sc, d);
        if (lane >= d) sc += t;
    }
    if (lane == 31) wtot[w] = sc;
    __syncthreads();
    int woff = 0;
#pragma unroll
    for (int t = 0; t < 8; t++) woff += (t < w) ? wtot[t] : 0;
    if (tid == 0) {
        int s = 0;
#pragma unroll
        for (int t = 0; t < 8; t++) s += wtot[t];
        d_gcnt[b] = (s < Gc) ? s : Gc;
    }
    int o = woff + sc - c;
#pragma unroll
    for (int i = 0; i < SEG; i++) {
        if (mv[i]) {
            if (o < Gc) d_gidx[b * Gc + o] = base + i;
            o++;
        }
    }
}

// ---------------------------------------------------------------------------
// Fused compute kernel with PACED embedded zero-fill.
// Each CTA owns 32 rows of the probs zero region (cols [128,2048)); each
// thread's 60 streaming stores are split into 4 chunks of 15, placed at
// phase boundaries so the DRAM drain proceeds under compute without the
// front-loaded burst hitting L2 write backpressure (R13: burst cost ~23us).
// Grid (32, H, B), 256 threads:
//   x in [0,16)  -> roleB: global-branch attn + probs cols [0,128) + ctx
//   x in [16,32) -> roleC: split-KV chunk of full attn for global queries
// ---------------------------------------------------------------------------
__global__ void __launch_bounds__(256, 2) fused_attn_kernel(
    const float* __restrict__ q, const float* __restrict__ k,
    const float* __restrict__ v, float* __restrict__ ctx,
    float* __restrict__ probs) {
    extern __shared__ float sm[];
    float* qsT    = sm;            // [64][128]
    float* ksT    = sm + 8192;     // [64][128]
    float* probsT = sm;            // [128 key][128 query], overlays after GEMM1
    float* gvs    = sm + 16384;    // [128][64]
    float* red    = sm + 24576;    // [128][17]
    float* linv   = sm + 26752;    // [128]

    int tid = threadIdx.x;
    int lane = tid & 31, w = tid >> 5;
    int h = blockIdx.y, b = blockIdx.z;
    int bh = b * Hc + h;

    // Fill-region coordinates for this thread (4 rows, 15 stores per row).
    int cid = blockIdx.x + 32 * (blockIdx.y + Hc * blockIdx.z);   // 0..767
    size_t fill_row0 = (size_t)cid * 32 + (size_t)w * 4;
    const float4 zf = make_float4(0.f, 0.f, 0.f, 0.f);

#define FILL_ROW(rr) do {                                                  \
        float4* p_ = (float4*)(probs + (fill_row0 + (rr)) * Sc + 128);     \
        _Pragma("unroll 3")                                                \
        for (int cc_ = lane; cc_ < 480; cc_ += 32) __stcs(p_ + cc_, zf);   \
    } while (0)

    // ---- fill chunk 0 (drains during the load phase)
    FILL_ROW(0);

    bool roleB = blockIdx.x < 16;
    int q0 = roleB ? blockIdx.x * QT : 0;
    int kc = roleB ? 0 : blockIdx.x - 16;
    int k0 = kc * 128;
    int c = d_gcnt[b];

    const float* qb = q + (size_t)bh * Sc * Dc;
    const float* kb = k + (size_t)bh * Sc * Dc;
    const float* vb = v + (size_t)bh * Sc * Dc;

    // ---- Load phase
    {
        int r = tid & 127, half = tid >> 7;
        int d0base = half * 32;

        bool qvalid = roleB || (r < c);
        int qrowi = roleB ? (q0 + r) : (qvalid ? d_gidx[b * Gc + r] : 0);
        const float* qrow = qb + (size_t)qrowi * Dc;
#pragma unroll
        for (int d0 = 0; d0 < 32; d0 += 4) {
            int dd = d0base + d0;
            float4 t = qvalid ? *(const float4*)(qrow + dd)
                              : make_float4(0.f, 0.f, 0.f, 0.f);
            qsT[(dd + 0) * 128 + r] = t.x;
            qsT[(dd + 1) * 128 + r] = t.y;
            qsT[(dd + 2) * 128 + r] = t.z;
            qsT[(dd + 3) * 128 + r] = t.w;
        }

        bool kvalid = roleB ? (r < c) : true;
        int krowi = roleB ? (kvalid ? d_gidx[b * Gc + r] : 0) : (k0 + r);
        const float* krow = kb + (size_t)krowi * Dc;
        const float* vrow = vb + (size_t)krowi * Dc;
#pragma unroll
        for (int d0 = 0; d0 < 32; d0 += 4) {
            int dd = d0base + d0;
            float4 t = kvalid ? *(const float4*)(krow + dd)
                              : make_float4(0.f, 0.f, 0.f, 0.f);
            ksT[(dd + 0) * 128 + r] = t.x;
            ksT[(dd + 1) * 128 + r] = t.y;
            ksT[(dd + 2) * 128 + r] = t.z;
            ksT[(dd + 3) * 128 + r] = t.w;
            *(float4*)(gvs + r * 64 + dd) = kvalid ? *(const float4*)(vrow + dd)
                                                   : make_float4(0.f, 0.f, 0.f, 0.f);
        }
    }

    // ---- fill chunk 1 (issued before the barrier; drains during GEMM1)
    FILL_ROW(1);
    __syncthreads();

    // ---- GEMM1: S^T[128 key][128 query], 8x8/thread, conflict-free.
    int qx = (lane & 7) | ((w & 1) << 3);
    int kg = (lane >> 3) | ((w >> 1) << 2);
    int kg8 = kg * 8, qx4 = qx * 4;

    int colw[8];
#pragma unroll
    for (int jj = 0; jj < 8; jj++) colw[jj] = (jj < 4) ? (qx4 + jj) : (60 + qx4 + jj);

    ull acc2[8][4];
#pragma unroll
    for (int i = 0; i < 8; i++)
#pragma unroll
        for (int jp = 0; jp < 4; jp++) acc2[i][jp] = 0ull;

#pragma unroll 8
    for (int d = 0; d < 64; d++) {
        const float4* kk = (const float4*)(ksT + d * 128 + kg8);
        float4 kv0 = kk[0], kv1 = kk[1];
        ull ap[8];
        ap[0] = pack2(kv0.x, kv0.x); ap[1] = pack2(kv0.y, kv0.y);
        ap[2] = pack2(kv0.z, kv0.z); ap[3] = pack2(kv0.w, kv0.w);
        ap[4] = pack2(kv1.x, kv1.x); ap[5] = pack2(kv1.y, kv1.y);
        ap[6] = pack2(kv1.z, kv1.z); ap[7] = pack2(kv1.w, kv1.w);
        ulonglong2 qA = *(const ulonglong2*)(qsT + d * 128 + qx4);
        ulonglong2 qB = *(const ulonglong2*)(qsT + d * 128 + 64 + qx4);
#pragma unroll
        for (int i = 0; i < 8; i++) {
            acc2[i][0] = fma2(ap[i], qA.x, acc2[i][0]);
            acc2[i][1] = fma2(ap[i], qA.y, acc2[i][1]);
            acc2[i][2] = fma2(ap[i], qB.x, acc2[i][2]);
            acc2[i][3] = fma2(ap[i], qB.y, acc2[i][3]);
        }
    }

    // ---- fill chunk 2 (drains during softmax + reductions)
    FILL_ROW(2);
    __syncthreads();   // all GEMM1 reads of qsT/ksT done before probsT overwrite

    // ---- softmax (no max-sub): exp in place, write probsT, column sums
    {
        float cs[8];
#pragma unroll
        for (int jj = 0; jj < 8; jj++) cs[jj] = 0.f;
#pragma unroll
        for (int i = 0; i < 8; i++) {
            bool kval = (!roleB) || (kg8 + i < c);
#pragma unroll
            for (int jp = 0; jp < 4; jp++) {
                float2 f = unpack2(acc2[i][jp]);
                float e0 = kval ? __expf(f.x * 0.125f) : 0.f;
                float e1 = kval ? __expf(f.y * 0.125f) : 0.f;
                acc2[i][jp] = pack2(e0, e1);
                cs[2 * jp]     += e0;
                cs[2 * jp + 1] += e1;
            }
            *(ulonglong2*)(probsT + (kg8 + i) * 128 + qx4) =
                make_ulonglong2(acc2[i][0], acc2[i][1]);
            *(ulonglong2*)(probsT + (kg8 + i) * 128 + 64 + qx4) =
                make_ulonglong2(acc2[i][2], acc2[i][3]);
        }
#pragma unroll
        for (int jj = 0; jj < 8; jj++) red[colw[jj] * 17 + kg] = cs[jj];
    }
    __syncthreads();
    if (tid < 128) {
        float rs = 0.f;
#pragma unroll
        for (int g = 0; g < 16; g++) rs += red[tid * 17 + g];
        linv[tid] = 1.0f / rs;
        if (!roleB) d_pl[((size_t)bh * KC + kc) * Gc + tid] = rs;
    }

    // ---- fill chunk 3 (drains during probs write + GEMM2)
    FILL_ROW(3);
    __syncthreads();

    // ---- probs gmem write straight from registers (roleB only)
    if (roleB) {
        float lv[8];
#pragma unroll
        for (int jj = 0; jj < 8; jj++) lv[jj] = linv[colw[jj]];
#pragma unroll
        for (int jp = 0; jp < 4; jp++) {
            float2 f[8];
#pragma unroll
            for (int i = 0; i < 8; i++) f[i] = unpack2(acc2[i][jp]);
            float l0 = lv[2 * jp], l1 = lv[2 * jp + 1];
            float* r0 = probs + ((size_t)bh * Sc + q0 + colw[2 * jp]) * Sc + kg8;
            float* r1 = probs + ((size_t)bh * Sc + q0 + colw[2 * jp + 1]) * Sc + kg8;
            __stcs((float4*)r0, make_float4(f[0].x * l0, f[1].x * l0, f[2].x * l0, f[3].x * l0));
            __stcs((float4*)(r0 + 4), make_float4(f[4].x * l0, f[5].x * l0, f[6].x * l0, f[7].x * l0));
            __stcs((float4*)r1, make_float4(f[0].y * l1, f[1].y * l1, f[2].y * l1, f[3].y * l1));
            __stcs((float4*)(r1 + 4), make_float4(f[4].y * l1, f[5].y * l1, f[6].y * l1, f[7].y * l1));
        }
    }

    // ---- GEMM2: C[128 q][64 d] = probsT^T @ V. 4 rows x 8 cols per thread.
    {
        int dg = lane & 7;
        int rg = (lane >> 3) | (w << 2);
        int dg4 = dg * 4, rg4 = rg * 4;

        ull ag[4][4];
#pragma unroll
        for (int r = 0; r < 4; r++)
#pragma unroll
            for (int p = 0; p < 4; p++) ag[r][p] = 0ull;

#pragma unroll 8
        for (int j = 0; j < 128; j++) {
            float4 av = *(const float4*)(probsT + j * 128 + rg4);
            ull p0 = pack2(av.x, av.x), p1 = pack2(av.y, av.y);
            ull p2 = pack2(av.z, av.z), p3 = pack2(av.w, av.w);
            ulonglong2 vA = *(const ulonglong2*)(gvs + j * 64 + dg4);
            ulonglong2 vB = *(const ulonglong2*)(gvs + j * 64 + 32 + dg4);
            ag[0][0] = fma2(p0, vA.x, ag[0][0]); ag[0][1] = fma2(p0, vA.y, ag[0][1]);
            ag[0][2] = fma2(p0, vB.x, ag[0][2]); ag[0][3] = fma2(p0, vB.y, ag[0][3]);
            ag[1][0] = fma2(p1, vA.x, ag[1][0]); ag[1][1] = fma2(p1, vA.y, ag[1][1]);
            ag[1][2] = fma2(p1, vB.x, ag[1][2]); ag[1][3] = fma2(p1, vB.y, ag[1][3]);
            ag[2][0] = fma2(p2, vA.x, ag[2][0]); ag[2][1] = fma2(p2, vA.y, ag[2][1]);
            ag[2][2] = fma2(p2, vB.x, ag[2][2]); ag[2][3] = fma2(p2, vB.y, ag[2][3]);
            ag[3][0] = fma2(p3, vA.x, ag[3][0]); ag[3][1] = fma2(p3, vA.y, ag[3][1]);
            ag[3][2] = fma2(p3, vB.x, ag[3][2]); ag[3][3] = fma2(p3, vB.y, ag[3][3]);
        }

        if (roleB) {
#pragma unroll
            for (int r = 0; r < 4; r++) {
                float lv = linv[rg4 + r];
                float* orow = ctx + ((size_t)bh * Sc + q0 + rg4 + r) * Dc;
                float2 f0 = unpack2(ag[r][0]), f1 = unpack2(ag[r][1]);
                float2 f2 = unpack2(ag[r][2]), f3 = unpack2(ag[r][3]);
                *(float4*)(orow + dg4) =
                    make_float4(f0.x * lv, f0.y * lv, f1.x * lv, f1.y * lv);
                *(float4*)(orow + 32 + dg4) =
                    make_float4(f2.x * lv, f2.y * lv, f3.x * lv, f3.y * lv);
            }
        } else {
#pragma unroll
            for (int r = 0; r < 4; r++) {
                float* orow = d_pacc + (((size_t)bh * KC + kc) * Gc + rg4 + r) * Dc;
                float2 f0 = unpack2(ag[r][0]), f1 = unpack2(ag[r][1]);
                float2 f2 = unpack2(ag[r][2]), f3 = unpack2(ag[r][3]);
                *(float4*)(orow + dg4) = make_float4(f0.x, f0.y, f1.x, f1.y);
                *(float4*)(orow + 32 + dg4) = make_float4(f2.x, f2.y, f3.x, f3.y);
            }
        }
    }
#undef FILL_ROW
}

// ---------------------------------------------------------------------------
// Combine: plain sum of KC split-KV partials.
// ---------------------------------------------------------------------------
__global__ void combine_kernel(float* __restrict__ ctx) {
    int bh = blockIdx.x;
    int b = bh / Hc;
    int c = d_gcnt[b];
    int tid = threadIdx.x;
    int rl = tid >> 4, seg = tid & 15;
    int r = blockIdx.y * 16 + rl;
    if (r >= c) return;

    float L = 0.f;
    float4 s = make_float4(0.f, 0.f, 0.f, 0.f);
#pragma unroll
    for (int kc = 0; kc < KC; kc++) {
        L += d_pl[((size_t)bh * KC + kc) * Gc + r];
        float4 g = *(const float4*)(d_pacc +
            (((size_t)bh * KC + kc) * Gc + r) * (size_t)Dc + seg * 4);
        s.x += g.x; s.y += g.y; s.z += g.z; s.w += g.w;
    }
    float inv = 1.0f / L;
    int gi = d_gidx[b * Gc + r];
    *(float4*)(ctx + ((size_t)bh * Sc + gi) * Dc + seg * 4) =
        make_float4(s.x * inv, s.y * inv, s.z * inv, s.w * inv);
}

// ---------------------------------------------------------------------------
extern "C" void kernel_launch(void* const* d_in, const int* in_sizes, int n_in,
                              void* d_out, int out_size) {
    const float* q = (const float*)d_in[0];
    const float* k = (const float*)d_in[1];
    const float* v = (const float*)d_in[2];
    const int* mask = (const int*)d_in[3];

    float* ctx = (float*)d_out;
    float* probs = ctx + CTX_ELEMS;

    cudaFuncSetAttribute(fused_attn_kernel,
                         cudaFuncAttributeMaxDynamicSharedMemorySize, SMEM_BYTES);

    dummy_kernel<<<1, 1>>>();                          // launch idx 0
    dummy_kernel<<<1, 1>>>();                          // launch idx 1
    build_index_kernel<<<Bc, 256>>>(mask);             // launch idx 2
    fused_attn_kernel<<<dim3(32, Hc, Bc), 256, SMEM_BYTES>>>(q, k, v, ctx, probs);  // idx 3 (ncu)
    combine_kernel<<<dim3(Bc * Hc, 8), 256>>>(ctx);    // launch idx 4
}